// round 14
// baseline (speedup 1.0000x reference)
#include <cuda_runtime.h>
#include <cuda_bf16.h>
#include <math.h>
#include <stdint.h>

constexpr int kD = 2048, kE = 32, kK = 8, kI = 1024, kMaxT = 8192;
constexpr int kMaxRows = kMaxT * kK;   // 65536

// ---------------- scratch ----------------
__device__ int   g_topi[kMaxRows];
__device__ float g_topw[kMaxRows];
__device__ int   g_rowtok[kMaxRows];
__device__ float g_rowscale[kMaxRows];
__device__ int   g_counts[kE];
__device__ int   g_offsets[kE + 1];
__device__ int   g_cursor[kE];
__device__ float g_sumprob[kE];
__device__ int   g_flag;
__device__ __align__(16) float g_H[(size_t)kMaxRows * kI];              // 256 MB
// pre-split operands (bf16 hi/lo, truncation split identical to pack2)
__device__ __align__(16) __nv_bfloat16 g_xhi[(size_t)kMaxT * kD];       // 32 MB
__device__ __align__(16) __nv_bfloat16 g_xlo[(size_t)kMaxT * kD];       // 32 MB
__device__ __align__(16) __nv_bfloat16 g_WgThi[(size_t)kE * kI * kD];   // 128 MB  [e][n][k]
__device__ __align__(16) __nv_bfloat16 g_WgTlo[(size_t)kE * kI * kD];   // 128 MB
__device__ __align__(16) __nv_bfloat16 g_WuThi[(size_t)kE * kI * kD];   // 128 MB
__device__ __align__(16) __nv_bfloat16 g_WuTlo[(size_t)kE * kI * kD];   // 128 MB

// ---------------- helpers ----------------
__device__ __forceinline__ uint32_t smem_u32(const void* p) {
    uint32_t a;
    asm("{ .reg .u64 t; cvta.to.shared.u64 t, %1; cvt.u32.u64 %0, t; }" : "=r"(a) : "l"(p));
    return a;
}
__device__ __forceinline__ void cp16(uint32_t dst, const void* src) {
    asm volatile("cp.async.cg.shared.global [%0], [%1], 16;" :: "r"(dst), "l"(src));
}
#define CP_COMMIT() asm volatile("cp.async.commit_group;" ::: "memory")
#define CP_WAIT1()  asm volatile("cp.async.wait_group 1;" ::: "memory")
__device__ __forceinline__ void mma_bf16(float* c, const uint32_t* a, const uint32_t* b) {
    asm volatile(
        "mma.sync.aligned.m16n8k16.row.col.f32.bf16.bf16.f32 "
        "{%0,%1,%2,%3}, {%4,%5,%6,%7}, {%8,%9}, {%0,%1,%2,%3};"
        : "+f"(c[0]), "+f"(c[1]), "+f"(c[2]), "+f"(c[3])
        : "r"(a[0]), "r"(a[1]), "r"(a[2]), "r"(a[3]), "r"(b[0]), "r"(b[1]));
}
__device__ __forceinline__ void pack2(float a, float b, uint32_t& hi, uint32_t& lo) {
    uint32_t ra = __float_as_uint(a), rb = __float_as_uint(b);
    asm("prmt.b32 %0, %1, %2, 0x7632;" : "=r"(hi) : "r"(ra), "r"(rb));
    float la = a - __uint_as_float(ra & 0xFFFF0000u);
    float lb = b - __uint_as_float(rb & 0xFFFF0000u);
    asm("prmt.b32 %0, %1, %2, 0x7632;" : "=r"(lo) : "r"(__float_as_uint(la)), "r"(__float_as_uint(lb)));
}
__device__ __forceinline__ void trunc_split(float v, __nv_bfloat16& h, __nv_bfloat16& l) {
    uint32_t b = __float_as_uint(v);
    h = __ushort_as_bfloat16((unsigned short)(b >> 16));
    float lo = v - __uint_as_float(b & 0xFFFF0000u);
    l = __ushort_as_bfloat16((unsigned short)(__float_as_uint(lo) >> 16));
}

// ---------------- launch 1: transpose+split Wg/Wu -> [e][n][k] bf16 hi/lo ----------------
__global__ void tsplit_kernel(const float* __restrict__ Wg, const float* __restrict__ Wu) {
    __shared__ float s[32][33];
    const int mat = blockIdx.z >> 5;          // 0 = Wg, 1 = Wu
    const int e = blockIdx.z & 31;
    const int c0 = blockIdx.x * 32, r0 = blockIdx.y * 32;   // c over kI, r over kD
    const float* W = (mat ? Wu : Wg) + (size_t)e * kD * kI;
    __nv_bfloat16* Th = (mat ? g_WuThi : g_WgThi) + (size_t)e * kI * kD;
    __nv_bfloat16* Tl = (mat ? g_WuTlo : g_WgTlo) + (size_t)e * kI * kD;
#pragma unroll
    for (int i = 0; i < 4; ++i)
        s[threadIdx.y + i * 8][threadIdx.x] =
            W[(size_t)(r0 + threadIdx.y + i * 8) * kI + c0 + threadIdx.x];
    __syncthreads();
#pragma unroll
    for (int i = 0; i < 4; ++i) {
        float v = s[threadIdx.x][threadIdx.y + i * 8];
        size_t o = (size_t)(c0 + threadIdx.y + i * 8) * kD + r0 + threadIdx.x;
        __nv_bfloat16 h, l;
        trunc_split(v, h, l);
        Th[o] = h;
        Tl[o] = l;
    }
}

// ---------------- launch 2: split x ----------------
__global__ void splitx_kernel(const float* __restrict__ x, size_t n) {
    size_t i = (size_t)blockIdx.x * blockDim.x + threadIdx.x;
    size_t stride = (size_t)gridDim.x * blockDim.x;
    for (; i < n; i += stride) {
        __nv_bfloat16 h, l;
        trunc_split(x[i], h, l);
        g_xhi[i] = h;
        g_xlo[i] = l;
    }
}

// ---------------- launch 3: zero out + reset ----------------
__global__ void zeroreset_kernel(float* __restrict__ out, size_t n) {
    size_t i = (size_t)blockIdx.x * blockDim.x + threadIdx.x;
    size_t stride = (size_t)gridDim.x * blockDim.x;
    for (; i < n; i += stride) out[i] = 0.f;
    if (blockIdx.x == 0) {
        if (threadIdx.x < kE) {
            g_counts[threadIdx.x] = 0;
            g_cursor[threadIdx.x] = 0;
            g_sumprob[threadIdx.x] = 0.f;
        }
        if (threadIdx.x == 0) g_flag = 0;
    }
}

// ---------------- launch 4: router ----------------
__global__ void router_kernel(const float* __restrict__ x,
                              const float* __restrict__ Wgate, int T) {
    int warp = (blockIdx.x * blockDim.x + threadIdx.x) >> 5;
    int lane = threadIdx.x & 31;
    if (warp >= T) return;
    const float* xt = x + (size_t)warp * kD;

    float acc = 0.f;
#pragma unroll 4
    for (int d = 0; d < kD; ++d) acc += xt[d] * Wgate[d * kE + lane];

    float m = acc;
#pragma unroll
    for (int o = 16; o; o >>= 1) m = fmaxf(m, __shfl_xor_sync(0xffffffffu, m, o));
    float p = __expf(acc - m);
    float s = p;
#pragma unroll
    for (int o = 16; o; o >>= 1) s += __shfl_xor_sync(0xffffffffu, s, o);
    atomicAdd(&g_sumprob[lane], p / s);

    float v = acc;
    float topv[kK]; int topi[kK];
#pragma unroll
    for (int k = 0; k < kK; ++k) {
        float bv = v; int bi = lane;
#pragma unroll
        for (int o = 16; o; o >>= 1) {
            float ov = __shfl_xor_sync(0xffffffffu, bv, o);
            int   oi = __shfl_xor_sync(0xffffffffu, bi, o);
            if (ov > bv || (ov == bv && oi < bi)) { bv = ov; bi = oi; }
        }
        topv[k] = bv; topi[k] = bi;
        if (lane == bi) v = -INFINITY;
    }

    float mx = topv[0];
    float w[kK]; float se = 0.f;
#pragma unroll
    for (int k = 0; k < kK; ++k) { w[k] = __expf(topv[k] - mx); se += w[k]; }
#pragma unroll
    for (int k = 0; k < kK; ++k) {
        if (lane == k) {
            g_topi[warp * kK + k] = topi[k];
            g_topw[warp * kK + k] = w[k] / se;
            atomicAdd(&g_counts[topi[k]], 1);
        }
    }
}

// ---------------- launch 5: offsets + aux then scatter (spin-gated) ----------------
__global__ void osa_kernel(float* __restrict__ out, int T, int out_size) {
    if (blockIdx.x == 0 && threadIdx.x == 0) {
        int s = 0;
        for (int e = 0; e < kE; ++e) { g_offsets[e] = s; s += g_counts[e]; }
        g_offsets[kE] = s;
        if ((size_t)out_size > (size_t)T * kD) {
            float a = 0.f;
            for (int e = 0; e < kE; ++e) a += g_sumprob[e] * (float)g_counts[e];
            out[(size_t)T * kD] = a / ((float)T * (float)T);
        }
        __threadfence();
        atomicExch(&g_flag, 1);
    } else {
        while (atomicAdd(&g_flag, 0) == 0) {}
    }
    __syncthreads();
    int idx = blockIdx.x * blockDim.x + threadIdx.x;
    if (idx < T * kK) {
        int e = g_topi[idx];
        int pos = g_offsets[e] + atomicAdd(&g_cursor[e], 1);
        g_rowtok[pos]   = idx / kK;
        g_rowscale[pos] = g_topw[idx];
    }
}

// =========================================================================
// GEMM1 (launch 6): 128(M) x 64(N), BK=16, 256 threads, 2 CTAs/SM.
// cp.async 3-stage ring (3 x 24576 B dynamic smem), NO pack/STS in mainloop.
// Stage layout (pitch 48 B per 16-k row): AH@0(6144) AL@6144 GH@12288(3072)
//   GL@15360 UH@18432 UL@21504. Fragment map: R10/R13-proven (unchanged).
// =========================================================================
constexpr int G1_STG = 24576;
__global__ __launch_bounds__(256, 2) void gemm1_mma() {
    extern __shared__ __align__(16) char sm[];
    __shared__ int   toks[128];
    __shared__ float scls[128];
    const int e = blockIdx.z;
    const int base  = g_offsets[e];
    const int count = g_offsets[e + 1] - base;
    const int m0 = blockIdx.y * 128;
    if (m0 >= count) return;
    const int n0 = blockIdx.x * 64;
    const int tid = threadIdx.x, lane = tid & 31, wid = tid >> 5;
    const int wm = wid & 3, wn = wid >> 2, g = lane >> 2, q = lane & 3;
    const uint32_t sb = smem_u32(sm);

    if (tid < 128) {
        int r = m0 + tid;
        toks[tid] = g_rowtok[base + ((r < count) ? r : (count - 1))];
        scls[tid] = (r < count) ? g_rowscale[base + r] : 0.f;
    }
    __syncthreads();

    // per-thread cp.async chunk descriptors (4 chunks of 16B per thread per stage)
    auto issue = [&](int s, int buf) {
        const int k0 = s * 16;
        const uint32_t bb = sb + buf * G1_STG;
#pragma unroll
        for (int i = 0; i < 4; ++i) {
            int c = tid + 256 * i;
            if (c < 512) {                       // A planes: hi then lo
                int p = c >> 8, d = c & 255;
                int r = d >> 1, half = d & 1;
                const __nv_bfloat16* src = (p ? g_xlo : g_xhi)
                    + (size_t)toks[r] * kD + k0 + half * 8;
                cp16(bb + p * 6144 + r * 48 + half * 16, src);
            } else {                             // B planes: GH GL UH UL
                int d = c - 512;
                int mat = d >> 8, dd = d & 255;
                int p = dd >> 7, f = dd & 127;
                int nn = f >> 1, half = f & 1;
                const __nv_bfloat16* src =
                    (mat ? (p ? g_WuTlo : g_WuThi) : (p ? g_WgTlo : g_WgThi))
                    + ((size_t)e * kI + n0 + nn) * kD + k0 + half * 8;
                cp16(bb + 12288 + mat * 6144 + p * 3072 + nn * 48 + half * 16, src);
            }
        }
    };

    float cg[2][4][4] = {}, cu[2][4][4] = {};
    const int S = kD / 16;   // 128
    issue(0, 0); CP_COMMIT();
    issue(1, 1); CP_COMMIT();
    CP_WAIT1();
    __syncthreads();

    for (int s = 0; s < S; ++s) {
        if (s + 2 < S) issue(s + 2, (s + 2) % 3);
        CP_COMMIT();
        const char* bb = sm + (s % 3) * G1_STG;
        uint32_t ah[2][4], al[2][4];
#pragma unroll
        for (int mt = 0; mt < 2; ++mt) {
            const char* o = bb + (wm * 32 + mt * 16 + g) * 48 + q * 4;
            ah[mt][0] = *(const uint32_t*)(o);
            ah[mt][1] = *(const uint32_t*)(o + 384);
            ah[mt][2] = *(const uint32_t*)(o + 16);
            ah[mt][3] = *(const uint32_t*)(o + 400);
            al[mt][0] = *(const uint32_t*)(o + 6144);
            al[mt][1] = *(const uint32_t*)(o + 6528);
            al[mt][2] = *(const uint32_t*)(o + 6160);
            al[mt][3] = *(const uint32_t*)(o + 6544);
        }
#pragma unroll
        for (int j = 0; j < 4; ++j) {
            const char* o = bb + 12288 + (wn * 32 + j * 8 + g) * 48 + q * 4;
            uint32_t gh[2] = { *(const uint32_t*)(o),         *(const uint32_t*)(o + 16) };
            uint32_t gl[2] = { *(const uint32_t*)(o + 3072),  *(const uint32_t*)(o + 3088) };
            uint32_t uh[2] = { *(const uint32_t*)(o + 6144),  *(const uint32_t*)(o + 6160) };
            uint32_t ul[2] = { *(const uint32_t*)(o + 9216),  *(const uint32_t*)(o + 9232) };
#pragma unroll
            for (int mt = 0; mt < 2; ++mt) {
                mma_bf16(cg[mt][j], ah[mt], gh);
                mma_bf16(cg[mt][j], ah[mt], gl);
                mma_bf16(cg[mt][j], al[mt], gh);
                mma_bf16(cu[mt][j], ah[mt], uh);
                mma_bf16(cu[mt][j], ah[mt], ul);
                mma_bf16(cu[mt][j], al[mt], uh);
            }
        }
        CP_WAIT1();
        __syncthreads();
    }

    // epilogue: H = silu(gate) * up * routing weight (fp32)
#pragma unroll
    for (int mt = 0; mt < 2; ++mt)
#pragma unroll
        for (int h = 0; h < 2; ++h) {
            int rl = wm * 32 + mt * 16 + g + h * 8;
            if (m0 + rl < count) {
                float sc = scls[rl];
                float* dst = g_H + (size_t)(base + m0 + rl) * kI + n0 + wn * 32 + q * 2;
#pragma unroll
                for (int j = 0; j < 4; ++j) {
                    float g0 = cg[mt][j][2 * h], g1 = cg[mt][j][2 * h + 1];
                    float u0 = cu[mt][j][2 * h], u1 = cu[mt][j][2 * h + 1];
                    float h0 = g0 / (1.f + __expf(-g0)) * u0 * sc;
                    float h1 = g1 / (1.f + __expf(-g1)) * u1 * sc;
                    *(float2*)(dst + j * 8) = make_float2(h0, h1);
                }
            }
        }
}

// =========================================================================
// GEMM2 (launch 7): R13-verbatim. 128x128, BK=16, 256 thr, 2 CTAs/SM,
// double-buffer one-sync. A=g_H fp32 + pack2, B=Wd fp32 + pack2. atomicAdd.
// =========================================================================
constexpr int G2_STG = 24576;
__global__ __launch_bounds__(256, 2) void gemm2_mma(float* __restrict__ out,
                                                    const float* __restrict__ Wd) {
    extern __shared__ __align__(16) char sm[];
    __shared__ int toks[128];
    const int e = blockIdx.z;
    const int base  = g_offsets[e];
    const int count = g_offsets[e + 1] - base;
    const int m0 = blockIdx.y * 128;
    if (m0 >= count) return;
    const int n0 = blockIdx.x * 128;
    const int tid = threadIdx.x, lane = tid & 31, wid = tid >> 5;
    const int wm = wid & 3, wn = wid >> 2, g = lane >> 2, q = lane & 3;

    if (tid < 128) {
        int r = m0 + tid;
        toks[tid] = g_rowtok[base + ((r < count) ? r : (count - 1))];
    }
    __syncthreads();

    const int arow = tid >> 1, ah8 = (tid & 1) * 8;
    const int bn = tid & 127, bk8 = (tid >> 7) * 8;
    const int arl = (m0 + arow < count) ? (m0 + arow) : (count - 1);
    const float* aptr = g_H + (size_t)(base + arl) * kI + ah8;

    float4 ra0, ra1;
    float rb[8];

    auto load = [&](int s) {
        const int k0 = s * 16;
        ra0 = *(const float4*)(aptr + k0);
        ra1 = *(const float4*)(aptr + k0 + 4);
        const float* bp = Wd + ((size_t)e * kI + k0 + bk8) * kD + n0 + bn;
#pragma unroll
        for (int i = 0; i < 8; ++i) rb[i] = bp[(size_t)i * kD];
    };
    auto store = [&](int buf) {
        char* bb = sm + buf * G2_STG;
        uint32_t h0, l0, h1, l1, h2, l2, h3, l3;
        {
            uint32_t o = (uint32_t)(arow * 48 + ah8 * 2);
            pack2(ra0.x, ra0.y, h0, l0);
            pack2(ra0.z, ra0.w, h1, l1);
            pack2(ra1.x, ra1.y, h2, l2);
            pack2(ra1.z, ra1.w, h3, l3);
            *(uint32_t*)(bb + o)             = h0;
            *(uint32_t*)(bb + o + 4)         = h1;
            *(uint32_t*)(bb + o + 8)         = h2;
            *(uint32_t*)(bb + o + 12)        = h3;
            *(uint32_t*)(bb + 6144 + o)      = l0;
            *(uint32_t*)(bb + 6144 + o + 4)  = l1;
            *(uint32_t*)(bb + 6144 + o + 8)  = l2;
            *(uint32_t*)(bb + 6144 + o + 12) = l3;
        }
        {
            uint32_t o = (uint32_t)(bn * 48 + bk8 * 2);
            pack2(rb[0], rb[1], h0, l0);
            pack2(rb[2], rb[3], h1, l1);
            pack2(rb[4], rb[5], h2, l2);
            pack2(rb[6], rb[7], h3, l3);
            *(uint32_t*)(bb + 12288 + o)      = h0;
            *(uint32_t*)(bb + 12288 + o + 4)  = h1;
            *(uint32_t*)(bb + 12288 + o + 8)  = h2;
            *(uint32_t*)(bb + 12288 + o + 12) = h3;
            *(uint32_t*)(bb + 18432 + o)      = l0;
            *(uint32_t*)(bb + 18432 + o + 4)  = l1;
            *(uint32_t*)(bb + 18432 + o + 8)  = l2;
            *(uint32_t*)(bb + 18432 + o + 12) = l3;
        }
    };

    float c[2][8][4] = {};
    load(0); store(0);
    __syncthreads();

    const int S = kI / 16;   // 64
    int buf = 0;
    for (int s = 0; s < S; ++s) {
        if (s + 1 < S) load(s + 1);
        const char* bb = sm + buf * G2_STG;
        uint32_t ah[2][4], al[2][4];
#pragma unroll
        for (int mt = 0; mt < 2; ++mt) {
            const char* o = bb + (wm * 32 + mt * 16 + g) * 48 + q * 4;
            ah[mt][0] = *(const uint32_t*)(o);
            ah[mt][1] = *(const uint32_t*)(o + 384);
            ah[mt][2] = *(const uint32_t*)(o + 16);
            ah[mt][3] = *(const uint32_t*)(o + 400);
            al[mt][0] = *(const uint32_t*)(o + 6144);
            al[mt][1] = *(const uint32_t*)(o + 6528);
            al[mt][2] = *(const uint32_t*)(o + 6160);
            al[mt][3] = *(const uint32_t*)(o + 6544);
        }
#pragma unroll
        for (int j = 0; j < 8; ++j) {
            const char* o = bb + 12288 + (wn * 64 + j * 8 + g) * 48 + q * 4;
            uint32_t bh[2] = { *(const uint32_t*)(o),        *(const uint32_t*)(o + 16) };
            uint32_t bl[2] = { *(const uint32_t*)(o + 6144), *(const uint32_t*)(o + 6160) };
#pragma unroll
            for (int mt = 0; mt < 2; ++mt) {
                mma_bf16(c[mt][j], ah[mt], bh);
                mma_bf16(c[mt][j], ah[mt], bl);
                mma_bf16(c[mt][j], al[mt], bh);
            }
        }
        if (s + 1 < S) store(buf ^ 1);
        __syncthreads();
        buf ^= 1;
    }

#pragma unroll
    for (int mt = 0; mt < 2; ++mt)
#pragma unroll
        for (int h = 0; h < 2; ++h) {
            int rl = wm * 32 + mt * 16 + g + h * 8;
            if (m0 + rl < count) {
                int tok = toks[rl];
                float* op = out + (size_t)tok * kD + n0 + wn * 64 + q * 2;
#pragma unroll
                for (int j = 0; j < 8; ++j) {
                    atomicAdd(&op[j * 8],     c[mt][j][2 * h]);
                    atomicAdd(&op[j * 8 + 1], c[mt][j][2 * h + 1]);
                }
            }
        }
}

// ---------------- launch ----------------
extern "C" void kernel_launch(void* const* d_in, const int* in_sizes, int n_in,
                              void* d_out, int out_size) {
    const float* x     = (const float*)d_in[0];
    const float* Wgate = (const float*)d_in[1];
    const float* Wg    = (const float*)d_in[2];
    const float* Wu    = (const float*)d_in[3];
    const float* Wd    = (const float*)d_in[4];
    float* out = (float*)d_out;

    const int T = in_sizes[0] / kD;

    cudaFuncSetAttribute(gemm1_mma, cudaFuncAttributeMaxDynamicSharedMemorySize, 3 * G1_STG);
    cudaFuncSetAttribute(gemm2_mma, cudaFuncAttributeMaxDynamicSharedMemorySize, 2 * G2_STG);

    tsplit_kernel<<<dim3(kI / 32, kD / 32, 2 * kE), dim3(32, 8)>>>(Wg, Wu);      // 1
    splitx_kernel<<<2048, 256>>>(x, (size_t)T * kD);                              // 2
    zeroreset_kernel<<<2048, 256>>>(out, (size_t)out_size);                       // 3
    router_kernel<<<(T + 7) / 8, 256>>>(x, Wgate, T);                             // 4
    osa_kernel<<<(T * kK + 255) / 256, 256>>>(out, T, out_size);                  // 5
    gemm1_mma<<<dim3(kI / 64, kMaxT / 128, kE), 256, 3 * G1_STG>>>();             // 6
    gemm2_mma<<<dim3(kD / 128, kMaxT / 128, kE), 256, 2 * G2_STG>>>(out, Wd);     // 7
}

// round 15
// speedup vs baseline: 1.1414x; 1.1414x over previous
#include <cuda_runtime.h>
#include <cuda_bf16.h>
#include <math.h>
#include <stdint.h>

constexpr int kD = 2048, kE = 32, kK = 8, kI = 1024, kMaxT = 8192;
constexpr int kMaxRows = kMaxT * kK;   // 65536

// ---------------- scratch ----------------
__device__ int   g_topi[kMaxRows];
__device__ float g_topw[kMaxRows];
__device__ int   g_rowtok[kMaxRows];
__device__ float g_rowscale[kMaxRows];
__device__ int   g_counts[kE];
__device__ int   g_offsets[kE + 1];
__device__ int   g_cursor[kE];
__device__ float g_sumprob[kE];
__device__ int   g_flag;
__device__ __align__(16) float g_H[(size_t)kMaxRows * kI];   // 256 MB scratch

// ---------------- helpers ----------------
__device__ __forceinline__ uint32_t smem_u32(const void* p) {
    uint32_t a;
    asm("{ .reg .u64 t; cvta.to.shared.u64 t, %1; cvt.u32.u64 %0, t; }" : "=r"(a) : "l"(p));
    return a;
}
__device__ __forceinline__ void mma_bf16(float* c, const uint32_t* a, const uint32_t* b) {
    asm volatile(
        "mma.sync.aligned.m16n8k16.row.col.f32.bf16.bf16.f32 "
        "{%0,%1,%2,%3}, {%4,%5,%6,%7}, {%8,%9}, {%0,%1,%2,%3};"
        : "+f"(c[0]), "+f"(c[1]), "+f"(c[2]), "+f"(c[3])
        : "r"(a[0]), "r"(a[1]), "r"(a[2]), "r"(a[3]), "r"(b[0]), "r"(b[1]));
}
__device__ __forceinline__ void ldsm4(uint32_t* r, uint32_t addr) {
    asm volatile("ldmatrix.sync.aligned.m8n8.x4.shared.b16 {%0,%1,%2,%3}, [%4];"
                 : "=r"(r[0]), "=r"(r[1]), "=r"(r[2]), "=r"(r[3]) : "r"(addr));
}
// Truncation-based hi/lo split of a float pair, packed as bf16x2.
__device__ __forceinline__ void pack2(float a, float b, uint32_t& hi, uint32_t& lo) {
    uint32_t ra = __float_as_uint(a), rb = __float_as_uint(b);
    asm("prmt.b32 %0, %1, %2, 0x7632;" : "=r"(hi) : "r"(ra), "r"(rb));
    float la = a - __uint_as_float(ra & 0xFFFF0000u);
    float lb = b - __uint_as_float(rb & 0xFFFF0000u);
    asm("prmt.b32 %0, %1, %2, 0x7632;" : "=r"(lo) : "r"(__float_as_uint(la)), "r"(__float_as_uint(lb)));
}

// ---------------- launch 1: zero out + reset bookkeeping ----------------
__global__ void zeroreset_kernel(float* __restrict__ out, size_t n) {
    size_t i = (size_t)blockIdx.x * blockDim.x + threadIdx.x;
    size_t stride = (size_t)gridDim.x * blockDim.x;
    for (; i < n; i += stride) out[i] = 0.f;
    if (blockIdx.x == 0) {
        if (threadIdx.x < kE) {
            g_counts[threadIdx.x] = 0;
            g_cursor[threadIdx.x] = 0;
            g_sumprob[threadIdx.x] = 0.f;
        }
        if (threadIdx.x == 0) g_flag = 0;
    }
}

// ---------------- launch 2: router ----------------
__global__ void router_kernel(const float* __restrict__ x,
                              const float* __restrict__ Wgate, int T) {
    int warp = (blockIdx.x * blockDim.x + threadIdx.x) >> 5;
    int lane = threadIdx.x & 31;
    if (warp >= T) return;
    const float* xt = x + (size_t)warp * kD;

    float acc = 0.f;
#pragma unroll 4
    for (int d = 0; d < kD; ++d) acc += xt[d] * Wgate[d * kE + lane];

    float m = acc;
#pragma unroll
    for (int o = 16; o; o >>= 1) m = fmaxf(m, __shfl_xor_sync(0xffffffffu, m, o));
    float p = __expf(acc - m);
    float s = p;
#pragma unroll
    for (int o = 16; o; o >>= 1) s += __shfl_xor_sync(0xffffffffu, s, o);
    atomicAdd(&g_sumprob[lane], p / s);

    float v = acc;
    float topv[kK]; int topi[kK];
#pragma unroll
    for (int k = 0; k < kK; ++k) {
        float bv = v; int bi = lane;
#pragma unroll
        for (int o = 16; o; o >>= 1) {
            float ov = __shfl_xor_sync(0xffffffffu, bv, o);
            int   oi = __shfl_xor_sync(0xffffffffu, bi, o);
            if (ov > bv || (ov == bv && oi < bi)) { bv = ov; bi = oi; }
        }
        topv[k] = bv; topi[k] = bi;
        if (lane == bi) v = -INFINITY;
    }

    float mx = topv[0];
    float w[kK]; float se = 0.f;
#pragma unroll
    for (int k = 0; k < kK; ++k) { w[k] = __expf(topv[k] - mx); se += w[k]; }
#pragma unroll
    for (int k = 0; k < kK; ++k) {
        if (lane == k) {
            g_topi[warp * kK + k] = topi[k];
            g_topw[warp * kK + k] = w[k] / se;
            atomicAdd(&g_counts[topi[k]], 1);
        }
    }
}

// ---------------- launch 3: offsets + aux (block0) then scatter (spin-gated) ----------------
__global__ void osa_kernel(float* __restrict__ out, int T, int out_size) {
    if (blockIdx.x == 0 && threadIdx.x == 0) {
        int s = 0;
        for (int e = 0; e < kE; ++e) { g_offsets[e] = s; s += g_counts[e]; }
        g_offsets[kE] = s;
        if ((size_t)out_size > (size_t)T * kD) {
            float a = 0.f;
            for (int e = 0; e < kE; ++e) a += g_sumprob[e] * (float)g_counts[e];
            out[(size_t)T * kD] = a / ((float)T * (float)T);
        }
        __threadfence();
        atomicExch(&g_flag, 1);
    } else {
        while (atomicAdd(&g_flag, 0) == 0) {}
    }
    __syncthreads();
    int idx = blockIdx.x * blockDim.x + threadIdx.x;
    if (idx < T * kK) {
        int e = g_topi[idx];
        int pos = g_offsets[e] + atomicAdd(&g_cursor[e], 1);
        g_rowtok[pos]   = idx / kK;
        g_rowscale[pos] = g_topw[idx];
    }
}

// =========================================================================
// GEMM1 (launch 4): 128(M) x 64(N), BK=16, 256 threads, 2 CTAs/SM, fused gate+up.
// DOUBLE-BUFFERED dynamic smem, ONE sync per stage. ldmatrix.x4 fragment loads.
//   stage = 24576 B: AH@0(6144) AL@6144 GH@12288(3072) GL@15360 UH@18432 UL@21504
// Warps: wm=wid&3 (32 rows), wn=wid>>2 in {0,1} (32 cols each).
// =========================================================================
constexpr int G1_STG = 24576;
__global__ __launch_bounds__(256, 2) void gemm1_mma(const float* __restrict__ x,
                                                    const float* __restrict__ Wg,
                                                    const float* __restrict__ Wu) {
    extern __shared__ __align__(16) char sm[];
    __shared__ int   toks[128];
    __shared__ float scls[128];
    const int e = blockIdx.z;
    const int base  = g_offsets[e];
    const int count = g_offsets[e + 1] - base;
    const int m0 = blockIdx.y * 128;
    if (m0 >= count) return;
    const int n0 = blockIdx.x * 64;
    const int tid = threadIdx.x, lane = tid & 31, wid = tid >> 5;
    const int wm = wid & 3, wn = wid >> 2, g = lane >> 2, q = lane & 3;
    const uint32_t sb = smem_u32(sm);

    if (tid < 128) {
        int r = m0 + tid;
        toks[tid] = g_rowtok[base + ((r < count) ? r : (count - 1))];
        scls[tid] = (r < count) ? g_rowscale[base + r] : 0.f;
    }
    __syncthreads();

    // ldmatrix lane-address offsets (R8-verified mapping)
    // A x4: m0=rows0-7/k0-7, m1=+8rows, m2=+8k, m3=both
    const uint32_t aoff = (uint32_t)((wm * 32 + (lane & 7) + ((lane >> 3) & 1) * 8) * 48
                                     + ((lane >> 4) & 1) * 16);
    // B x4: m0=n0-7/k0-7, m1=n0-7/k8-15, m2=n8-15/k0-7, m3=n8-15/k8-15
    const uint32_t boff = (uint32_t)((wn * 32 + (lane & 7) + ((lane >> 4) & 1) * 8) * 48
                                     + ((lane >> 3) & 1) * 16);

    const int arow = tid >> 1, ah8 = (tid & 1) * 8;       // A: 128 rows, 8-k halves
    const int bn = tid & 63, bk8 = ((tid >> 6) & 1) * 8;  // B: 64 n, 8-k halves
    const int bmat = tid >> 7;                             // 0 = gate, 1 = up

    float4 ra0, ra1;
    float rb[8];

    auto load = [&](int s) {
        const int k0 = s * 16;
        const float* ap = x + (size_t)toks[arow] * kD + k0 + ah8;
        ra0 = *(const float4*)(ap);
        ra1 = *(const float4*)(ap + 4);
        const float* bp = (bmat ? Wu : Wg) + ((size_t)e * kD + k0 + bk8) * kI + n0 + bn;
#pragma unroll
        for (int i = 0; i < 8; ++i) rb[i] = bp[(size_t)i * kI];
    };
    auto store = [&](int buf) {
        char* bb = sm + buf * G1_STG;
        uint32_t h0, l0, h1, l1, h2, l2, h3, l3;
        {
            uint32_t o = (uint32_t)(arow * 48 + ah8 * 2);
            pack2(ra0.x, ra0.y, h0, l0);
            pack2(ra0.z, ra0.w, h1, l1);
            pack2(ra1.x, ra1.y, h2, l2);
            pack2(ra1.z, ra1.w, h3, l3);
            *(uint32_t*)(bb + o)             = h0;
            *(uint32_t*)(bb + o + 4)         = h1;
            *(uint32_t*)(bb + o + 8)         = h2;
            *(uint32_t*)(bb + o + 12)        = h3;
            *(uint32_t*)(bb + 6144 + o)      = l0;
            *(uint32_t*)(bb + 6144 + o + 4)  = l1;
            *(uint32_t*)(bb + 6144 + o + 8)  = l2;
            *(uint32_t*)(bb + 6144 + o + 12) = l3;
        }
        {
            uint32_t bofs = 12288 + (uint32_t)bmat * 6144;
            uint32_t o = (uint32_t)(bn * 48 + bk8 * 2);
            pack2(rb[0], rb[1], h0, l0);
            pack2(rb[2], rb[3], h1, l1);
            pack2(rb[4], rb[5], h2, l2);
            pack2(rb[6], rb[7], h3, l3);
            *(uint32_t*)(bb + bofs + o)             = h0;
            *(uint32_t*)(bb + bofs + o + 4)         = h1;
            *(uint32_t*)(bb + bofs + o + 8)         = h2;
            *(uint32_t*)(bb + bofs + o + 12)        = h3;
            *(uint32_t*)(bb + bofs + 3072 + o)      = l0;
            *(uint32_t*)(bb + bofs + 3072 + o + 4)  = l1;
            *(uint32_t*)(bb + bofs + 3072 + o + 8)  = l2;
            *(uint32_t*)(bb + bofs + 3072 + o + 12) = l3;
        }
    };

    float cg[2][4][4] = {}, cu[2][4][4] = {};
    load(0); store(0);
    __syncthreads();

    const int S = kD / 16;   // 128
    int buf = 0;
    for (int s = 0; s < S; ++s) {
        if (s + 1 < S) load(s + 1);
        const uint32_t bbu = sb + buf * G1_STG;
        uint32_t ah[2][4], al[2][4];
#pragma unroll
        for (int mt = 0; mt < 2; ++mt) {
            ldsm4(ah[mt], bbu + aoff + mt * 768);
            ldsm4(al[mt], bbu + 6144 + aoff + mt * 768);
        }
#pragma unroll
        for (int jp = 0; jp < 2; ++jp) {
            uint32_t gh[4], gl[4], uh[4], ul[4];
            ldsm4(gh, bbu + 12288 + boff + jp * 768);
            ldsm4(gl, bbu + 15360 + boff + jp * 768);
            ldsm4(uh, bbu + 18432 + boff + jp * 768);
            ldsm4(ul, bbu + 21504 + boff + jp * 768);
#pragma unroll
            for (int mt = 0; mt < 2; ++mt) {
                mma_bf16(cg[mt][jp * 2],     ah[mt], &gh[0]);
                mma_bf16(cg[mt][jp * 2],     ah[mt], &gl[0]);
                mma_bf16(cg[mt][jp * 2],     al[mt], &gh[0]);
                mma_bf16(cg[mt][jp * 2 + 1], ah[mt], &gh[2]);
                mma_bf16(cg[mt][jp * 2 + 1], ah[mt], &gl[2]);
                mma_bf16(cg[mt][jp * 2 + 1], al[mt], &gh[2]);
                mma_bf16(cu[mt][jp * 2],     ah[mt], &uh[0]);
                mma_bf16(cu[mt][jp * 2],     ah[mt], &ul[0]);
                mma_bf16(cu[mt][jp * 2],     al[mt], &uh[0]);
                mma_bf16(cu[mt][jp * 2 + 1], ah[mt], &uh[2]);
                mma_bf16(cu[mt][jp * 2 + 1], ah[mt], &ul[2]);
                mma_bf16(cu[mt][jp * 2 + 1], al[mt], &uh[2]);
            }
        }
        if (s + 1 < S) store(buf ^ 1);
        __syncthreads();
        buf ^= 1;
    }

    // epilogue: H = silu(gate) * up * routing weight
#pragma unroll
    for (int mt = 0; mt < 2; ++mt)
#pragma unroll
        for (int h = 0; h < 2; ++h) {
            int rl = wm * 32 + mt * 16 + g + h * 8;
            if (m0 + rl < count) {
                float sc = scls[rl];
                float* dst = g_H + (size_t)(base + m0 + rl) * kI + n0 + wn * 32 + q * 2;
#pragma unroll
                for (int j = 0; j < 4; ++j) {
                    float g0 = cg[mt][j][2 * h], g1 = cg[mt][j][2 * h + 1];
                    float u0 = cu[mt][j][2 * h], u1 = cu[mt][j][2 * h + 1];
                    float h0 = g0 / (1.f + __expf(-g0)) * u0 * sc;
                    float h1 = g1 / (1.f + __expf(-g1)) * u1 * sc;
                    *(float2*)(dst + j * 8) = make_float2(h0, h1);
                }
            }
        }
}

// =========================================================================
// GEMM2 (launch 5): 128(M) x 128(N), BK=16, 256 threads, 2 CTAs/SM.
// DOUBLE-BUFFERED dynamic smem, ONE sync per stage. ldmatrix.x4 loads.
//   stage = 24576 B: AH@0 AL@6144 BH@12288 BL@18432. atomicAdd epilogue.
// Warps: wm=wid&3 (32 rows), wn=wid>>2 in {0,1} (64 cols, 4 j-pairs).
// =========================================================================
constexpr int G2_STG = 24576;
__global__ __launch_bounds__(256, 2) void gemm2_mma(float* __restrict__ out,
                                                    const float* __restrict__ Wd) {
    extern __shared__ __align__(16) char sm[];
    __shared__ int toks[128];
    const int e = blockIdx.z;
    const int base  = g_offsets[e];
    const int count = g_offsets[e + 1] - base;
    const int m0 = blockIdx.y * 128;
    if (m0 >= count) return;
    const int n0 = blockIdx.x * 128;
    const int tid = threadIdx.x, lane = tid & 31, wid = tid >> 5;
    const int wm = wid & 3, wn = wid >> 2, g = lane >> 2, q = lane & 3;
    const uint32_t sb = smem_u32(sm);

    if (tid < 128) {
        int r = m0 + tid;
        toks[tid] = g_rowtok[base + ((r < count) ? r : (count - 1))];
    }
    __syncthreads();

    const uint32_t aoff = (uint32_t)((wm * 32 + (lane & 7) + ((lane >> 3) & 1) * 8) * 48
                                     + ((lane >> 4) & 1) * 16);
    const uint32_t boff = (uint32_t)((wn * 64 + (lane & 7) + ((lane >> 4) & 1) * 8) * 48
                                     + ((lane >> 3) & 1) * 16);

    const int arow = tid >> 1, ah8 = (tid & 1) * 8;
    const int bn = tid & 127, bk8 = (tid >> 7) * 8;
    const int arl = (m0 + arow < count) ? (m0 + arow) : (count - 1);
    const float* aptr = g_H + (size_t)(base + arl) * kI + ah8;

    float4 ra0, ra1;
    float rb[8];

    auto load = [&](int s) {
        const int k0 = s * 16;
        ra0 = *(const float4*)(aptr + k0);
        ra1 = *(const float4*)(aptr + k0 + 4);
        const float* bp = Wd + ((size_t)e * kI + k0 + bk8) * kD + n0 + bn;
#pragma unroll
        for (int i = 0; i < 8; ++i) rb[i] = bp[(size_t)i * kD];
    };
    auto store = [&](int buf) {
        char* bb = sm + buf * G2_STG;
        uint32_t h0, l0, h1, l1, h2, l2, h3, l3;
        {
            uint32_t o = (uint32_t)(arow * 48 + ah8 * 2);
            pack2(ra0.x, ra0.y, h0, l0);
            pack2(ra0.z, ra0.w, h1, l1);
            pack2(ra1.x, ra1.y, h2, l2);
            pack2(ra1.z, ra1.w, h3, l3);
            *(uint32_t*)(bb + o)             = h0;
            *(uint32_t*)(bb + o + 4)         = h1;
            *(uint32_t*)(bb + o + 8)         = h2;
            *(uint32_t*)(bb + o + 12)        = h3;
            *(uint32_t*)(bb + 6144 + o)      = l0;
            *(uint32_t*)(bb + 6144 + o + 4)  = l1;
            *(uint32_t*)(bb + 6144 + o + 8)  = l2;
            *(uint32_t*)(bb + 6144 + o + 12) = l3;
        }
        {
            uint32_t o = (uint32_t)(bn * 48 + bk8 * 2);
            pack2(rb[0], rb[1], h0, l0);
            pack2(rb[2], rb[3], h1, l1);
            pack2(rb[4], rb[5], h2, l2);
            pack2(rb[6], rb[7], h3, l3);
            *(uint32_t*)(bb + 12288 + o)      = h0;
            *(uint32_t*)(bb + 12288 + o + 4)  = h1;
            *(uint32_t*)(bb + 12288 + o + 8)  = h2;
            *(uint32_t*)(bb + 12288 + o + 12) = h3;
            *(uint32_t*)(bb + 18432 + o)      = l0;
            *(uint32_t*)(bb + 18432 + o + 4)  = l1;
            *(uint32_t*)(bb + 18432 + o + 8)  = l2;
            *(uint32_t*)(bb + 18432 + o + 12) = l3;
        }
    };

    float c[2][8][4] = {};
    load(0); store(0);
    __syncthreads();

    const int S = kI / 16;   // 64
    int buf = 0;
    for (int s = 0; s < S; ++s) {
        if (s + 1 < S) load(s + 1);
        const uint32_t bbu = sb + buf * G2_STG;
        uint32_t ah[2][4], al[2][4];
#pragma unroll
        for (int mt = 0; mt < 2; ++mt) {
            ldsm4(ah[mt], bbu + aoff + mt * 768);
            ldsm4(al[mt], bbu + 6144 + aoff + mt * 768);
        }
#pragma unroll
        for (int jp = 0; jp < 4; ++jp) {
            uint32_t bh[4], bl[4];
            ldsm4(bh, bbu + 12288 + boff + jp * 768);
            ldsm4(bl, bbu + 18432 + boff + jp * 768);
#pragma unroll
            for (int mt = 0; mt < 2; ++mt) {
                mma_bf16(c[mt][jp * 2],     ah[mt], &bh[0]);
                mma_bf16(c[mt][jp * 2],     ah[mt], &bl[0]);
                mma_bf16(c[mt][jp * 2],     al[mt], &bh[0]);
                mma_bf16(c[mt][jp * 2 + 1], ah[mt], &bh[2]);
                mma_bf16(c[mt][jp * 2 + 1], ah[mt], &bl[2]);
                mma_bf16(c[mt][jp * 2 + 1], al[mt], &bh[2]);
            }
        }
        if (s + 1 < S) store(buf ^ 1);
        __syncthreads();
        buf ^= 1;
    }

#pragma unroll
    for (int mt = 0; mt < 2; ++mt)
#pragma unroll
        for (int h = 0; h < 2; ++h) {
            int rl = wm * 32 + mt * 16 + g + h * 8;
            if (m0 + rl < count) {
                int tok = toks[rl];
                float* op = out + (size_t)tok * kD + n0 + wn * 64 + q * 2;
#pragma unroll
                for (int j = 0; j < 8; ++j) {
                    atomicAdd(&op[j * 8],     c[mt][j][2 * h]);
                    atomicAdd(&op[j * 8 + 1], c[mt][j][2 * h + 1]);
                }
            }
        }
}

// ---------------- launch ----------------
extern "C" void kernel_launch(void* const* d_in, const int* in_sizes, int n_in,
                              void* d_out, int out_size) {
    const float* x     = (const float*)d_in[0];
    const float* Wgate = (const float*)d_in[1];
    const float* Wg    = (const float*)d_in[2];
    const float* Wu    = (const float*)d_in[3];
    const float* Wd    = (const float*)d_in[4];
    float* out = (float*)d_out;

    const int T = in_sizes[0] / kD;

    cudaFuncSetAttribute(gemm1_mma, cudaFuncAttributeMaxDynamicSharedMemorySize, 2 * G1_STG);
    cudaFuncSetAttribute(gemm2_mma, cudaFuncAttributeMaxDynamicSharedMemorySize, 2 * G2_STG);

    zeroreset_kernel<<<2048, 256>>>(out, (size_t)out_size);                 // launch 1
    router_kernel<<<(T + 7) / 8, 256>>>(x, Wgate, T);                       // launch 2
    osa_kernel<<<(T * kK + 255) / 256, 256>>>(out, T, out_size);            // launch 3
    gemm1_mma<<<dim3(kI / 64, kMaxT / 128, kE), 256, 2 * G1_STG>>>(x, Wg, Wu);   // launch 4
    gemm2_mma<<<dim3(kD / 128, kMaxT / 128, kE), 256, 2 * G2_STG>>>(out, Wd);    // launch 5
}